// round 9
// baseline (speedup 1.0000x reference)
#include <cuda_runtime.h>
#include <math.h>

// ---------------- problem constants ----------------
#define K_EMB   8192
#define D_EMB   256
#define N_TOK   16384          // 16 * 32 * 32
#define HW      1024           // 32*32
#define BATCH   16
#define QST_N   4194304        // 16*256*32*32

// output layout (concatenated float32, reference tuple order)
#define OFF_LOSS  0LL
#define OFF_QST   1LL
#define OFF_PERP  4194305LL
#define OFF_EMBO  4194306LL
#define OFF_CS    6291458LL
#define OFF_EMAW  6299650LL
#define OFF_IDX   8396802LL

// ---------------- scratch (static device memory; no allocations) ----------------
__device__ float g_counts[K_EMB];
__device__ float g_dw[K_EMB * D_EMB];
__device__ float g_esq[K_EMB];
__device__ float g_cs_pre[K_EMB];
__device__ int   g_idx[N_TOK];
__device__ float g_scal[3];   // [0]=loss sum, [1]=ntot, [2]=sum p*log(p)

typedef unsigned long long ull;

// packed fp32x2 FMA (Blackwell FFMA2)
__device__ __forceinline__ void ffma2(ull& acc, ull a, ull b) {
    asm("fma.rn.f32x2 %0, %1, %2, %0;" : "+l"(acc) : "l"(a), "l"(b));
}

// ---------------- kernel 0: zero scratch ----------------
__global__ void vq_zero_kernel() {
    int gi = blockIdx.x * blockDim.x + threadIdx.x;   // grid covers 2097152 exactly
    g_dw[gi] = 0.0f;
    if (gi < K_EMB) g_counts[gi] = 0.0f;
    if (gi < 3)     g_scal[gi]   = 0.0f;
}

// ---------------- kernel 1: ||e_k||^2 ----------------
__global__ void vq_esq_kernel(const float* __restrict__ emb) {
    int gi   = blockIdx.x * blockDim.x + threadIdx.x;
    int k    = gi >> 5;
    int lane = gi & 31;
    const float4* p = reinterpret_cast<const float4*>(emb + (size_t)k * D_EMB + lane * 8);
    float4 a = p[0], b = p[1];
    float s = a.x*a.x + a.y*a.y + a.z*a.z + a.w*a.w
            + b.x*b.x + b.y*b.y + b.z*b.z + b.w*b.w;
    #pragma unroll
    for (int o = 16; o > 0; o >>= 1) s += __shfl_down_sync(0xffffffffu, s, o);
    if (lane == 0) g_esq[k] = s;
}

// ---------------- kernel 2: fused distance GEMM + argmin ----------------
// CTA: 128 tokens x all 8192 codes. A tile resident in smem (fp32, [256][128]).
// B streamed in 8-d chunks, stored DUPLICATED as float2 so the f32x2 broadcast
// operand needs no packing. Accumulators paired along M.
__global__ void __launch_bounds__(256, 1)
vq_argmin_kernel(const float* __restrict__ x, const float* __restrict__ emb,
                 float* __restrict__ idx_f_out)
{
    extern __shared__ float smem[];
    float*  As   = smem;                                   // 32768 floats
    float2* Bs   = reinterpret_cast<float2*>(smem + 32768); // 2048 float2 (2 buf x 8 d x 128 n)
    float*  redv = smem + 32768 + 4096;                     // 2048 floats
    int*    redi = reinterpret_cast<int*>(smem + 32768 + 4096 + 2048);

    const int tid = threadIdx.x;
    const int tm  = tid >> 4;     // 0..15 -> 8 token rows each
    const int tn  = tid & 15;     // 0..15 -> 8 code cols each
    const int m0  = blockIdx.x << 7;
    const int b   = m0 >> 10;
    const float* xb = x + (size_t)b * (D_EMB * HW) + (m0 & 1023);

    // load A tile: As[d][m] = x[b][d][hw0+m]  (fully coalesced)
    #pragma unroll 4
    for (int i = tid; i < 256 * 32; i += 256) {
        int d = i >> 5, mq = i & 31;
        *reinterpret_cast<float4*>(&As[d * 128 + mq * 4]) =
            *reinterpret_cast<const float4*>(xb + (size_t)d * HW + mq * 4);
    }

    float bv[8]; int bi[8];
    #pragma unroll
    for (int i = 0; i < 8; i++) { bv[i] = 3.4e38f; bi[i] = 0; }

    const int c = tid >> 1;       // code row within tile this thread loads
    const int h = tid & 1;        // which half (4 d-values) of the 8-d chunk

    for (int nt = 0; nt < 64; ++nt) {
        const int k0 = nt << 7;
        const float* eb = emb + (((size_t)(k0 + c)) << 8) + (h << 2);

        ull acc[4][8];
        #pragma unroll
        for (int i = 0; i < 4; i++)
            #pragma unroll
            for (int j = 0; j < 8; j++) acc[i][j] = 0ULL;

        // prefetch chunk 0 into buffer 0
        {
            float4 r = *reinterpret_cast<const float4*>(eb);
            int base = (h << 2) * 128 + c;
            Bs[base      ] = make_float2(r.x, r.x);
            Bs[base + 128] = make_float2(r.y, r.y);
            Bs[base + 256] = make_float2(r.z, r.z);
            Bs[base + 384] = make_float2(r.w, r.w);
        }
        __syncthreads();

        for (int dc = 0; dc < 32; ++dc) {
            float4 rn;
            if (dc < 31) rn = *reinterpret_cast<const float4*>(eb + (dc + 1) * 8);
            const int cur = dc & 1;
            #pragma unroll
            for (int dd = 0; dd < 8; ++dd) {
                const int drow = (dc << 3) + dd;
                const ull* ap = reinterpret_cast<const ull*>(&As[drow * 128 + (tm << 3)]);
                ulonglong2 a01 = *reinterpret_cast<const ulonglong2*>(ap);
                ulonglong2 a23 = *reinterpret_cast<const ulonglong2*>(ap + 2);
                const ull* bp = reinterpret_cast<const ull*>(&Bs[cur * 1024 + dd * 128 + (tn << 3)]);
                ulonglong2 b01 = *reinterpret_cast<const ulonglong2*>(bp);
                ulonglong2 b23 = *reinterpret_cast<const ulonglong2*>(bp + 2);
                ulonglong2 b45 = *reinterpret_cast<const ulonglong2*>(bp + 4);
                ulonglong2 b67 = *reinterpret_cast<const ulonglong2*>(bp + 6);
                ull av[4] = { a01.x, a01.y, a23.x, a23.y };
                ull bw[8] = { b01.x, b01.y, b23.x, b23.y, b45.x, b45.y, b67.x, b67.y };
                #pragma unroll
                for (int i2 = 0; i2 < 4; i2++)
                    #pragma unroll
                    for (int n = 0; n < 8; n++)
                        ffma2(acc[i2][n], av[i2], bw[n]);
            }
            if (dc < 31) {
                int base = (cur ^ 1) * 1024 + (h << 2) * 128 + c;
                Bs[base      ] = make_float2(rn.x, rn.x);
                Bs[base + 128] = make_float2(rn.y, rn.y);
                Bs[base + 256] = make_float2(rn.z, rn.z);
                Bs[base + 384] = make_float2(rn.w, rn.w);
                __syncthreads();
            }
        }

        // epilogue: dist = ||e||^2 - 2*dot ; running argmin
        float4 e0 = *reinterpret_cast<const float4*>(&g_esq[k0 + (tn << 3)]);
        float4 e1 = *reinterpret_cast<const float4*>(&g_esq[k0 + (tn << 3) + 4]);
        float ev[8] = { e0.x, e0.y, e0.z, e0.w, e1.x, e1.y, e1.z, e1.w };
        #pragma unroll
        for (int i2 = 0; i2 < 4; i2++)
            #pragma unroll
            for (int n = 0; n < 8; n++) {
                ull a = acc[i2][n];
                float lo = __uint_as_float((unsigned)(a & 0xffffffffULL));
                float hi = __uint_as_float((unsigned)(a >> 32));
                float dl = ev[n] - 2.0f * lo;
                float dh = ev[n] - 2.0f * hi;
                int kk = k0 + (tn << 3) + n;
                if (dl < bv[2 * i2    ]) { bv[2 * i2    ] = dl; bi[2 * i2    ] = kk; }
                if (dh < bv[2 * i2 + 1]) { bv[2 * i2 + 1] = dh; bi[2 * i2 + 1] = kk; }
            }
    }

    // cross-thread reduction over tn for each token row
    __syncthreads();
    #pragma unroll
    for (int i = 0; i < 8; i++) {
        int m = (tm << 3) + i;
        redv[m * 16 + tn] = bv[i];
        redi[m * 16 + tn] = bi[i];
    }
    __syncthreads();
    if (tid < 128) {
        float best = redv[tid * 16];
        int   bidx = redi[tid * 16];
        #pragma unroll
        for (int t = 1; t < 16; t++) {
            float v = redv[tid * 16 + t];
            int   ii = redi[tid * 16 + t];
            if (v < best || (v == best && ii < bidx)) { best = v; bidx = ii; }
        }
        g_idx[m0 + tid] = bidx;
        idx_f_out[m0 + tid] = (float)bidx;
    }
}

// ---------------- kernel 3: gather q_st, loss, counts, dw ----------------
// block (32,8): tx = hw within 32-chunk (coalesced x read / q write), ty = d stripe
__global__ void vq_quant_kernel(const float* __restrict__ x,
                                const float* __restrict__ emb,
                                float* __restrict__ outq)
{
    const int tx = threadIdx.x, ty = threadIdx.y;
    const int hw = blockIdx.x * 32 + tx;
    const int b  = blockIdx.y;
    const int n  = (b << 10) + hw;
    const int code = g_idx[n];
    const float* erow = emb + ((size_t)code << 8);
    float lsum = 0.0f;
    for (int d = ty; d < D_EMB; d += 8) {
        size_t xi = (((size_t)(b * D_EMB + d)) << 10) + hw;
        float xv = x[xi];
        float q  = __ldg(erow + d);
        outq[xi] = q;
        atomicAdd(&g_dw[(code << 8) + d], xv);
        float df = q - xv;
        lsum += df * df;
    }
    if (ty == 0) atomicAdd(&g_counts[code], 1.0f);

    __shared__ float s[256];
    int t = ty * 32 + tx;
    s[t] = lsum;
    __syncthreads();
    #pragma unroll
    for (int st = 128; st > 0; st >>= 1) {
        if (t < st) s[t] += s[t + st];
        __syncthreads();
    }
    if (t == 0) atomicAdd(&g_scal[0], s[0]);
}

// ---------------- kernel 4: EMA stage 1 (cs_pre, ntot, perplexity sum) --------
__global__ void vq_ema1_kernel(const float* __restrict__ ecs) {
    int k = blockIdx.x * 256 + threadIdx.x;   // grid 32 x 256 = 8192
    float cnt = g_counts[k];
    float pre = ecs[k] * 0.99f + 0.01f * cnt;
    g_cs_pre[k] = pre;
    float p  = cnt * (1.0f / 16384.0f);
    float pl = p * logf(p + 1e-10f);

    __shared__ float sp[256], sl[256];
    int t = threadIdx.x;
    sp[t] = pre; sl[t] = pl;
    __syncthreads();
    #pragma unroll
    for (int st = 128; st > 0; st >>= 1) {
        if (t < st) { sp[t] += sp[t + st]; sl[t] += sl[t + st]; }
        __syncthreads();
    }
    if (t == 0) { atomicAdd(&g_scal[1], sp[0]); atomicAdd(&g_scal[2], sl[0]); }
}

// ---------------- kernel 5: EMA stage 2 (finalize all outputs) ----------------
__global__ void vq_ema2_kernel(const float* __restrict__ emaw, float* __restrict__ out) {
    int k = blockIdx.x;          // 8192
    int d = threadIdx.x;         // 256
    float ntot = g_scal[1];
    float ncs  = (g_cs_pre[k] + 1e-5f) / (ntot + 8192.0f * 1e-5f) * ntot;
    int i = (k << 8) + d;
    float nw = emaw[i] * 0.99f + 0.01f * g_dw[i];
    out[OFF_EMBO + i] = nw / ncs;
    out[OFF_EMAW + i] = nw;
    if (d == 0) out[OFF_CS + k] = ncs;
    if (k == 0 && d == 0) {
        out[OFF_LOSS] = 0.25f * g_scal[0] * (1.0f / 4194304.0f);
        out[OFF_PERP] = expf(-g_scal[2]);
    }
}

// ---------------- launch ----------------
extern "C" void kernel_launch(void* const* d_in, const int* in_sizes, int n_in,
                              void* d_out, int out_size)
{
    const float* x = nullptr; const float* emb = nullptr;
    const float* ecs = nullptr; const float* emaw = nullptr;
    for (int i = 0; i < n_in; i++) {
        int s = in_sizes[i];
        if (s == QST_N) x = (const float*)d_in[i];
        else if (s == K_EMB) ecs = (const float*)d_in[i];
        else if (s == K_EMB * D_EMB) {
            if (!emb) emb = (const float*)d_in[i];
            else emaw = (const float*)d_in[i];
        }
    }
    // fallback to positional order if anything missing
    if (!x)    x    = (const float*)d_in[0];
    if (!emb)  emb  = (const float*)d_in[1];
    if (!ecs)  ecs  = (const float*)d_in[2];
    if (!emaw) emaw = (const float*)d_in[3];
    float* out = (float*)d_out;

    static const size_t ARGMIN_SMEM = (32768 + 4096 + 2048 + 2048) * sizeof(float); // 163840 B
    cudaFuncSetAttribute(vq_argmin_kernel,
                         cudaFuncAttributeMaxDynamicSharedMemorySize,
                         (int)ARGMIN_SMEM);

    vq_zero_kernel<<<2048, 1024>>>();
    vq_esq_kernel<<<1024, 256>>>(emb);
    vq_argmin_kernel<<<128, 256, ARGMIN_SMEM>>>(x, emb, out + OFF_IDX);
    vq_quant_kernel<<<dim3(32, 16), dim3(32, 8)>>>(x, emb, out + OFF_QST);
    vq_ema1_kernel<<<32, 256>>>(ecs);
    vq_ema2_kernel<<<8192, 256>>>(emaw, out);
    (void)out_size;
}

// round 10
// speedup vs baseline: 3.3808x; 3.3808x over previous
#include <cuda_runtime.h>
#include <math.h>

// ---------------- problem constants ----------------
#define K_EMB   8192
#define D_EMB   256
#define N_TOK   16384          // 16 * 32 * 32
#define HW      1024           // 32*32
#define BATCH   16
#define QST_N   4194304        // 16*256*32*32

// output layout (concatenated float32, reference tuple order)
#define OFF_LOSS  0LL
#define OFF_QST   1LL
#define OFF_PERP  4194305LL
#define OFF_EMBO  4194306LL
#define OFF_CS    6291458LL
#define OFF_EMAW  6299650LL
#define OFF_IDX   8396802LL

// ---------------- scratch (static device memory; no allocations) ----------------
__device__ float g_counts[K_EMB];
__device__ float g_dw[K_EMB * D_EMB];
__device__ float g_esq[K_EMB];
__device__ float g_cs_pre[K_EMB];
__device__ int   g_idx[N_TOK];
__device__ float g_scal[3];   // [0]=loss sum, [1]=ntot, [2]=sum p*log(p)

typedef unsigned long long ull;

// packed fp32x2 FMA (Blackwell FFMA2)
__device__ __forceinline__ void ffma2(ull& acc, ull a, ull b) {
    asm("fma.rn.f32x2 %0, %1, %2, %0;" : "+l"(acc) : "l"(a), "l"(b));
}
// build (v, v) packed pair
__device__ __forceinline__ ull dup2(float v) {
    ull r; unsigned u = __float_as_uint(v);
    asm("mov.b64 %0, {%1, %2};" : "=l"(r) : "r"(u), "r"(u));
    return r;
}

// ---------------- kernel 0: zero scratch ----------------
__global__ void vq_zero_kernel() {
    int gi = blockIdx.x * blockDim.x + threadIdx.x;   // grid covers 2097152 exactly
    g_dw[gi] = 0.0f;
    if (gi < K_EMB) g_counts[gi] = 0.0f;
    if (gi < 3)     g_scal[gi]   = 0.0f;
}

// ---------------- kernel 1: ||e_k||^2 ----------------
__global__ void vq_esq_kernel(const float* __restrict__ emb) {
    int gi   = blockIdx.x * blockDim.x + threadIdx.x;
    int k    = gi >> 5;
    int lane = gi & 31;
    const float4* p = reinterpret_cast<const float4*>(emb + (size_t)k * D_EMB + lane * 8);
    float4 a = p[0], b = p[1];
    float s = a.x*a.x + a.y*a.y + a.z*a.z + a.w*a.w
            + b.x*b.x + b.y*b.y + b.z*b.z + b.w*b.w;
    #pragma unroll
    for (int o = 16; o > 0; o >>= 1) s += __shfl_down_sync(0xffffffffu, s, o);
    if (lane == 0) g_esq[k] = s;
}

// ---------------- kernel 2: fused distance GEMM + argmin ----------------
// CTA: 128 tokens x all 8192 codes. A tile resident in smem ([256 d][128 m]).
// Thread tile: 16 tokens (8 natural M-pairs) x 4 codes.
// Accumulators are M-paired ulls; A pairs load as aligned 64-bit from smem
// (conflict-free broadcast); B is plain float, one coalesced LDS.128 per
// thread per d-step (conflict-free), duplicated into (b,b) pairs in regs.
// B streamed double-buffered in 16-d chunks (compute per chunk > L2 latency).
__global__ void __launch_bounds__(256, 1)
vq_argmin_kernel(const float* __restrict__ x, const float* __restrict__ emb,
                 float* __restrict__ idx_f_out)
{
    extern __shared__ float smem[];
    float* As   = smem;                       // [256][128]         131072 B
    float* Bs   = smem + 32768;               // [2][16][128]        16384 B
    float* redv = smem + 32768 + 4096;        // [128][32]           16384 B
    int*   redi = reinterpret_cast<int*>(smem + 32768 + 4096 + 4096); // 16384 B

    const int tid = threadIdx.x;
    const int tn  = tid & 31;     // 4 codes: tn*4 .. tn*4+3
    const int tm  = tid >> 5;     // 16 tokens: tm*16 .. tm*16+15
    const int m0  = blockIdx.x << 7;
    const int b   = m0 >> 10;
    const float* xb = x + (size_t)b * (D_EMB * HW) + (m0 & 1023);

    // load A tile: As[d][m] = x[b][d][hw0+m]  (fully coalesced)
    #pragma unroll 4
    for (int i = tid; i < 256 * 32; i += 256) {
        int d = i >> 5, mq = i & 31;
        *reinterpret_cast<float4*>(&As[d * 128 + mq * 4]) =
            *reinterpret_cast<const float4*>(xb + (size_t)d * HW + mq * 4);
    }

    float bv[16]; int bi[16];
    #pragma unroll
    for (int i = 0; i < 16; i++) { bv[i] = 3.4e38f; bi[i] = 0; }

    // B producer mapping: thread (c, h) loads 8 d-values of code row c per chunk
    const int c = tid >> 1;       // code row within 128-tile
    const int h = tid & 1;        // which 8-d half of the 16-d chunk

    for (int nt = 0; nt < 64; ++nt) {
        const int k0 = nt << 7;
        const float* eb = emb + (((size_t)(k0 + c)) << 8) + (h << 3);

        ull acc[8][4];
        #pragma unroll
        for (int i = 0; i < 8; i++)
            #pragma unroll
            for (int j = 0; j < 4; j++) acc[i][j] = 0ULL;

        // prefetch chunk 0 into buffer 0
        {
            float4 p0 = *reinterpret_cast<const float4*>(eb);
            float4 p1 = *reinterpret_cast<const float4*>(eb + 4);
            float v[8] = { p0.x, p0.y, p0.z, p0.w, p1.x, p1.y, p1.z, p1.w };
            #pragma unroll
            for (int j = 0; j < 8; j++) Bs[((h << 3) + j) * 128 + c] = v[j];
        }
        __syncthreads();

        for (int ch = 0; ch < 16; ++ch) {
            float4 q0, q1;
            if (ch < 15) {
                q0 = *reinterpret_cast<const float4*>(eb + (ch + 1) * 16);
                q1 = *reinterpret_cast<const float4*>(eb + (ch + 1) * 16 + 4);
            }
            const int cur = ch & 1;
            const float* Bc = Bs + cur * 2048;
            #pragma unroll
            for (int dd = 0; dd < 16; ++dd) {
                const int drow = (ch << 4) + dd;
                // A: 8 natural M-pairs (broadcast within warp, conflict-free)
                const ulonglong2* ap =
                    reinterpret_cast<const ulonglong2*>(&As[drow * 128 + (tm << 4)]);
                ulonglong2 a01 = ap[0], a23 = ap[1], a45 = ap[2], a67 = ap[3];
                ull av[8] = { a01.x, a01.y, a23.x, a23.y, a45.x, a45.y, a67.x, a67.y };
                // B: 4 codes, one coalesced LDS.128 (lane*16B, conflict-free)
                float4 bb = *reinterpret_cast<const float4*>(&Bc[dd * 128 + (tn << 2)]);
                ull bd[4] = { dup2(bb.x), dup2(bb.y), dup2(bb.z), dup2(bb.w) };
                #pragma unroll
                for (int mp = 0; mp < 8; mp++)
                    #pragma unroll
                    for (int n = 0; n < 4; n++)
                        ffma2(acc[mp][n], av[mp], bd[n]);
            }
            if (ch < 15) {
                float* Bn = Bs + (cur ^ 1) * 2048;
                float v[8] = { q0.x, q0.y, q0.z, q0.w, q1.x, q1.y, q1.z, q1.w };
                #pragma unroll
                for (int j = 0; j < 8; j++) Bn[((h << 3) + j) * 128 + c] = v[j];
                __syncthreads();
            }
        }

        // epilogue: dist = ||e||^2 - 2*dot ; running argmin (codes ascending)
        float4 e = *reinterpret_cast<const float4*>(&g_esq[k0 + (tn << 2)]);
        float ev[4] = { e.x, e.y, e.z, e.w };
        #pragma unroll
        for (int mp = 0; mp < 8; mp++)
            #pragma unroll
            for (int n = 0; n < 4; n++) {
                ull a = acc[mp][n];
                float lo = __uint_as_float((unsigned)(a & 0xffffffffULL));
                float hi = __uint_as_float((unsigned)(a >> 32));
                float dl = ev[n] - 2.0f * lo;
                float dh = ev[n] - 2.0f * hi;
                int kk = k0 + (tn << 2) + n;
                if (dl < bv[2 * mp    ]) { bv[2 * mp    ] = dl; bi[2 * mp    ] = kk; }
                if (dh < bv[2 * mp + 1]) { bv[2 * mp + 1] = dh; bi[2 * mp + 1] = kk; }
            }
        // next nt writes buffer 0 while stragglers may still read buffer 1:
        // disjoint regions, and the post-store __syncthreads realigns everyone.
    }

    // cross-thread reduction over tn (32 candidates per token)
    __syncthreads();
    #pragma unroll
    for (int i = 0; i < 16; i++) {
        int m = (tm << 4) + i;
        redv[m * 32 + tn] = bv[i];
        redi[m * 32 + tn] = bi[i];
    }
    __syncthreads();
    if (tid < 128) {
        float best = redv[tid * 32];
        int   bidx = redi[tid * 32];
        #pragma unroll
        for (int t = 1; t < 32; t++) {
            float v  = redv[tid * 32 + t];
            int   ii = redi[tid * 32 + t];
            if (v < best || (v == best && ii < bidx)) { best = v; bidx = ii; }
        }
        g_idx[m0 + tid] = bidx;
        idx_f_out[m0 + tid] = (float)bidx;
    }
}

// ---------------- kernel 3: gather q_st, loss, counts, dw ----------------
__global__ void vq_quant_kernel(const float* __restrict__ x,
                                const float* __restrict__ emb,
                                float* __restrict__ outq)
{
    const int tx = threadIdx.x, ty = threadIdx.y;
    const int hw = blockIdx.x * 32 + tx;
    const int b  = blockIdx.y;
    const int n  = (b << 10) + hw;
    const int code = g_idx[n];
    const float* erow = emb + ((size_t)code << 8);
    float lsum = 0.0f;
    for (int d = ty; d < D_EMB; d += 8) {
        size_t xi = (((size_t)(b * D_EMB + d)) << 10) + hw;
        float xv = x[xi];
        float q  = __ldg(erow + d);
        outq[xi] = q;
        atomicAdd(&g_dw[(code << 8) + d], xv);
        float df = q - xv;
        lsum += df * df;
    }
    if (ty == 0) atomicAdd(&g_counts[code], 1.0f);

    __shared__ float s[256];
    int t = ty * 32 + tx;
    s[t] = lsum;
    __syncthreads();
    #pragma unroll
    for (int st = 128; st > 0; st >>= 1) {
        if (t < st) s[t] += s[t + st];
        __syncthreads();
    }
    if (t == 0) atomicAdd(&g_scal[0], s[0]);
}

// ---------------- kernel 4: EMA stage 1 (cs_pre, ntot, perplexity sum) --------
__global__ void vq_ema1_kernel(const float* __restrict__ ecs) {
    int k = blockIdx.x * 256 + threadIdx.x;   // grid 32 x 256 = 8192
    float cnt = g_counts[k];
    float pre = ecs[k] * 0.99f + 0.01f * cnt;
    g_cs_pre[k] = pre;
    float p  = cnt * (1.0f / 16384.0f);
    float pl = p * logf(p + 1e-10f);

    __shared__ float sp[256], sl[256];
    int t = threadIdx.x;
    sp[t] = pre; sl[t] = pl;
    __syncthreads();
    #pragma unroll
    for (int st = 128; st > 0; st >>= 1) {
        if (t < st) { sp[t] += sp[t + st]; sl[t] += sl[t + st]; }
        __syncthreads();
    }
    if (t == 0) { atomicAdd(&g_scal[1], sp[0]); atomicAdd(&g_scal[2], sl[0]); }
}

// ---------------- kernel 5: EMA stage 2 (finalize all outputs) ----------------
__global__ void vq_ema2_kernel(const float* __restrict__ emaw, float* __restrict__ out) {
    int k = blockIdx.x;          // 8192
    int d = threadIdx.x;         // 256
    float ntot = g_scal[1];
    float ncs  = (g_cs_pre[k] + 1e-5f) / (ntot + 8192.0f * 1e-5f) * ntot;
    int i = (k << 8) + d;
    float nw = emaw[i] * 0.99f + 0.01f * g_dw[i];
    out[OFF_EMBO + i] = nw / ncs;
    out[OFF_EMAW + i] = nw;
    if (d == 0) out[OFF_CS + k] = ncs;
    if (k == 0 && d == 0) {
        out[OFF_LOSS] = 0.25f * g_scal[0] * (1.0f / 4194304.0f);
        out[OFF_PERP] = expf(-g_scal[2]);
    }
}

// ---------------- launch ----------------
extern "C" void kernel_launch(void* const* d_in, const int* in_sizes, int n_in,
                              void* d_out, int out_size)
{
    const float* x = nullptr; const float* emb = nullptr;
    const float* ecs = nullptr; const float* emaw = nullptr;
    for (int i = 0; i < n_in; i++) {
        int s = in_sizes[i];
        if (s == QST_N) x = (const float*)d_in[i];
        else if (s == K_EMB) ecs = (const float*)d_in[i];
        else if (s == K_EMB * D_EMB) {
            if (!emb) emb = (const float*)d_in[i];
            else emaw = (const float*)d_in[i];
        }
    }
    if (!x)    x    = (const float*)d_in[0];
    if (!emb)  emb  = (const float*)d_in[1];
    if (!ecs)  ecs  = (const float*)d_in[2];
    if (!emaw) emaw = (const float*)d_in[3];
    float* out = (float*)d_out;

    static const size_t ARGMIN_SMEM = (32768 + 4096 + 4096 + 4096) * sizeof(float); // 180224 B
    cudaFuncSetAttribute(vq_argmin_kernel,
                         cudaFuncAttributeMaxDynamicSharedMemorySize,
                         (int)ARGMIN_SMEM);

    vq_zero_kernel<<<2048, 1024>>>();
    vq_esq_kernel<<<1024, 256>>>(emb);
    vq_argmin_kernel<<<128, 256, ARGMIN_SMEM>>>(x, emb, out + OFF_IDX);
    vq_quant_kernel<<<dim3(32, 16), dim3(32, 8)>>>(x, emb, out + OFF_QST);
    vq_ema1_kernel<<<32, 256>>>(ecs);
    vq_ema2_kernel<<<8192, 256>>>(emaw, out);
    (void)out_size;
}